// round 5
// baseline (speedup 1.0000x reference)
#include <cuda_runtime.h>
#include <cuda_bf16.h>
#include <math.h>

#define NTOK 4096
#define HDIM 128
#define NHEAD 8
#define HEADD 16
#define FFDIM 256
#define NLAYER 4
#define QKVDIM 384
#define LATD 16
#define MAXN 512
#define BK 16

// ---------------- scratch (device globals; no runtime allocation) ----------------
__device__ float g_x[NTOK * HDIM];
__device__ float g_qkv[NTOK * QKVDIM];
__device__ float g_attn[NTOK * HDIM];
__device__ float g_ff[NTOK * FFDIM];
__device__ float g_mean[NTOK];
__device__ float g_rstd[NTOK];
__device__ float g_eta[NTOK];
__device__ float g_phi[NTOK];
__device__ int   g_nbr[NTOK * MAXN];
__device__ int   g_cnt[NTOK];

// ---------------- eta/phi precompute ----------------
__global__ void etaphi_kernel(const float* __restrict__ x_raw) {
    int i = blockIdx.x * blockDim.x + threadIdx.x;
    if (i >= NTOK) return;
    g_eta[i] = x_raw[i * 16 + 1] * 5.24f + (-2.62f);
    g_phi[i] = x_raw[i * 16 + 2] * 6.2832f + (-3.1416f);
}

// ---------------- neighbor list build (coarse wrap filter + exact trig confirm) --
__global__ void nbr_kernel() {
    int i = blockIdx.x;
    __shared__ int cnt;
    if (threadIdx.x == 0) cnt = 0;
    __syncthreads();
    const float ei = g_eta[i], pi_ = g_phi[i];
    const float TWO_PI = 6.2831853071795864769f;
    const float PI_ = 3.14159265358979323846f;
    for (int j = threadIdx.x; j < NTOK; j += blockDim.x) {
        float de = ei - g_eta[j];
        float dpr = pi_ - g_phi[j];
        float dpw = dpr;
        if (dpw > PI_) dpw -= TWO_PI;
        else if (dpw < -PI_) dpw += TWO_PI;
        float coarse = de * de + dpw * dpw;
        if (coarse <= 0.0404f) {
            float dp = atan2f(sinf(dpr), cosf(dpr));
            float s2 = __fadd_rn(__fmul_rn(de, de), __fmul_rn(dp, dp));
            if (sqrtf(s2) <= 0.2f) {
                int p = atomicAdd(&cnt, 1);
                if (p < MAXN) g_nbr[i * MAXN + p] = j;
            }
        }
    }
    __syncthreads();
    if (threadIdx.x == 0) g_cnt[i] = (cnt < MAXN) ? cnt : MAXN;
}

// =================================================================================
// Fused GEMM: C[M,NC] = op(A)[M,K] @ W[NC,K]^T + bias  (+ReLU) (+residual g_x)
//   LNA:   A is layernorm(g_x) applied on-the-fly with (g_mean,g_rstd,ln_s,ln_b)
//   STATS: epilogue computes per-row mean/rstd of C (requires BN == NC, TN == 32)
//   SRC:   0=Aext  1=g_x  2=g_attn  3=g_ff       DST: 0=g_x  1=g_qkv  2=g_ff
// 256 threads, per-thread 4x4 outputs, double-buffered smem, compile-time dims.
// =================================================================================
template <int M, int NC, int K, int BM, int BN,
          int LNA, int RELU, int RES, int STATS, int SRC, int DST>
__global__ __launch_bounds__(256) void gemm2(
    const float* __restrict__ Aext, const float* __restrict__ W,
    const float* __restrict__ bias,
    const float* __restrict__ ln_s, const float* __restrict__ ln_b) {

    constexpr int TN = BN / 4;          // threads along n
    constexpr int TM = 256 / TN;        // threads along m
    static_assert(TM * 4 == BM && TN * 4 == BN, "tile mismatch");
    constexpr int AF = BM * BK / 256;   // floats per thread per A-tile load
    constexpr int WF = BN * BK / 256;   // floats per thread per W-tile load
    constexpr int NK = K / BK;

    __shared__ float As[2][BK][BM + 4];
    __shared__ float Ws[2][BK][BN + 4];

    const float* A = (SRC == 0) ? Aext : (SRC == 1) ? g_x : (SRC == 2) ? g_attn : g_ff;
    float* C = (DST == 0) ? g_x : (DST == 1) ? g_qkv : g_ff;

    const int tid = threadIdx.x;
    const int m0 = blockIdx.y * BM, n0 = blockIdx.x * BN;
    const int tm = tid / TN, tn = tid % TN;

    const int arow = tid / (BK / AF);
    const int acol = (tid % (BK / AF)) * AF;
    const int wrow = tid / (BK / WF);
    const int wcol = (tid % (BK / WF)) * WF;

    const int agr = m0 + arow;
    const int wgr = n0 + wrow;
    float amu = 0.f, ars = 0.f;
    if (LNA) { amu = g_mean[agr]; ars = g_rstd[agr]; }

    float pa[AF], pw[WF];

    // prefetch tile 0
    #pragma unroll
    for (int c = 0; c < AF; c++) {
        float v = A[agr * K + acol + c];
        if (LNA) v = (v - amu) * ars * ln_s[acol + c] + ln_b[acol + c];
        pa[c] = v;
    }
    #pragma unroll
    for (int c = 0; c < WF; c++) pw[c] = W[wgr * K + wcol + c];
    #pragma unroll
    for (int c = 0; c < AF; c++) As[0][acol + c][arow] = pa[c];
    #pragma unroll
    for (int c = 0; c < WF; c++) Ws[0][wcol + c][wrow] = pw[c];
    __syncthreads();

    float acc[4][4];
    #pragma unroll
    for (int a = 0; a < 4; a++)
        #pragma unroll
        for (int b = 0; b < 4; b++) acc[a][b] = 0.0f;

    #pragma unroll 2
    for (int t = 0; t < NK; t++) {
        const int st = t & 1;
        if (t + 1 < NK) {
            const int k0 = (t + 1) * BK;
            #pragma unroll
            for (int c = 0; c < AF; c++) {
                float v = A[agr * K + k0 + acol + c];
                if (LNA) v = (v - amu) * ars * ln_s[k0 + acol + c] + ln_b[k0 + acol + c];
                pa[c] = v;
            }
            #pragma unroll
            for (int c = 0; c < WF; c++) pw[c] = W[wgr * K + k0 + wcol + c];
        }
        #pragma unroll
        for (int kk = 0; kk < BK; kk++) {
            float4 a4 = *reinterpret_cast<const float4*>(&As[st][kk][tm * 4]);
            float4 b4 = *reinterpret_cast<const float4*>(&Ws[st][kk][tn * 4]);
            float av[4] = {a4.x, a4.y, a4.z, a4.w};
            float bv[4] = {b4.x, b4.y, b4.z, b4.w};
            #pragma unroll
            for (int a = 0; a < 4; a++)
                #pragma unroll
                for (int b = 0; b < 4; b++) acc[a][b] += av[a] * bv[b];
        }
        if (t + 1 < NK) {
            const int ns = st ^ 1;
            #pragma unroll
            for (int c = 0; c < AF; c++) As[ns][acol + c][arow] = pa[c];
            #pragma unroll
            for (int c = 0; c < WF; c++) Ws[ns][wcol + c][wrow] = pw[c];
        }
        __syncthreads();
    }

    // epilogue
    float vals[4][4];
    #pragma unroll
    for (int a = 0; a < 4; a++) {
        const int m = m0 + tm * 4 + a;
        #pragma unroll
        for (int b = 0; b < 4; b++) {
            const int n = n0 + tn * 4 + b;
            float v = acc[a][b] + bias[n];
            if (RELU) v = fmaxf(v, 0.0f);
            if (RES) v += g_x[m * NC + n];
            vals[a][b] = v;
        }
        float4 o = make_float4(vals[a][0], vals[a][1], vals[a][2], vals[a][3]);
        *reinterpret_cast<float4*>(&C[m * NC + (n0 + tn * 4)]) = o;
    }

    if (STATS) {
        // BN == NC, TN == 32: warp tm owns rows m0+tm*4 .. +3 completely
        #pragma unroll
        for (int a = 0; a < 4; a++) {
            float s = vals[a][0] + vals[a][1] + vals[a][2] + vals[a][3];
            float q = vals[a][0] * vals[a][0] + vals[a][1] * vals[a][1] +
                      vals[a][2] * vals[a][2] + vals[a][3] * vals[a][3];
            #pragma unroll
            for (int o = 16; o; o >>= 1) {
                s += __shfl_xor_sync(0xffffffffu, s, o);
                q += __shfl_xor_sync(0xffffffffu, q, o);
            }
            if ((tid & 31) == 0) {
                const int m = m0 + tm * 4 + a;
                float mean = s * (1.0f / NC);
                float var = q * (1.0f / NC) - mean * mean;
                g_mean[m] = mean;
                g_rstd[m] = rsqrtf(var + 1e-5f);
            }
        }
    }
}

// ---------------- sparse gather attention: one block per query, 128 threads ------
__global__ void attn_kernel() {
    int i = blockIdx.x;
    int hd = threadIdx.x;  // head*16 + d == tid since H = NH*HD = 128

    const float* qkv = g_qkv;
    float qv = qkv[i * QKVDIM + hd];
    int cnt = g_cnt[i];
    const int* nb = &g_nbr[i * MAXN];

    float m = -1e30f, ssum = 0.0f, acc = 0.0f;
    for (int n = 0; n < cnt; n++) {
        int j = nb[n];
        float kv = qkv[j * QKVDIM + HDIM + hd];
        float vv = qkv[j * QKVDIM + 2 * HDIM + hd];
        float p = qv * kv;
        p += __shfl_xor_sync(0xffffffffu, p, 8, 16);
        p += __shfl_xor_sync(0xffffffffu, p, 4, 16);
        p += __shfl_xor_sync(0xffffffffu, p, 2, 16);
        p += __shfl_xor_sync(0xffffffffu, p, 1, 16);
        float s = p * 0.25f;  // 1/sqrt(16)
        float nm = fmaxf(m, s);
        float corr = expf(m - nm);
        float e = expf(s - nm);
        ssum = ssum * corr + e;
        acc = acc * corr + e * vv;
        m = nm;
    }
    g_attn[i * HDIM + hd] = acc / ssum;
}

// ---------------- lat head ----------------
__global__ void lat_head_kernel(const float* __restrict__ w1, const float* __restrict__ b1,
                                const float* __restrict__ w2, const float* __restrict__ b2,
                                float* __restrict__ out) {
    int row = blockIdx.x;
    int tid = threadIdx.x;  // 128
    __shared__ float xs[HDIM];
    __shared__ float t1[HDIM];
    xs[tid] = g_x[row * HDIM + tid];
    __syncthreads();
    float acc = b1[tid];
    const float* wr = &w1[tid * HDIM];
    #pragma unroll 8
    for (int k = 0; k < HDIM; k++) acc += xs[k] * wr[k];
    t1[tid] = fmaxf(acc, 0.0f);
    __syncthreads();
    if (tid < LATD) {
        float a = b2[tid];
        const float* wr2 = &w2[tid * HDIM];
        #pragma unroll 8
        for (int k = 0; k < HDIM; k++) a += t1[k] * wr2[k];
        float q = a * a;
        q += __shfl_xor_sync(0xffffffffu, q, 8, 16);
        q += __shfl_xor_sync(0xffffffffu, q, 4, 16);
        q += __shfl_xor_sync(0xffffffffu, q, 2, 16);
        q += __shfl_xor_sync(0xffffffffu, q, 1, 16);
        float nrm = fmaxf(sqrtf(q), 1e-12f);
        out[row * LATD + tid] = a / nrm;
    }
}

// ---------------- beta head ----------------
__global__ void beta_head_kernel(const float* __restrict__ w1, const float* __restrict__ b1,
                                 const float* __restrict__ w2, const float* __restrict__ b2,
                                 float* __restrict__ out) {
    int row = blockIdx.x;
    int tid = threadIdx.x;  // 128
    __shared__ float xs[HDIM];
    xs[tid] = g_x[row * HDIM + tid];
    __syncthreads();
    float p = 0.0f;
    if (tid < 64) {
        float acc = b1[tid];
        const float* wr = &w1[tid * HDIM];
        #pragma unroll 8
        for (int k = 0; k < HDIM; k++) acc += xs[k] * wr[k];
        p = fmaxf(acc, 0.0f) * w2[tid];
    }
    #pragma unroll
    for (int o = 16; o; o >>= 1) p += __shfl_xor_sync(0xffffffffu, p, o);
    __shared__ float wsum[4];
    if ((tid & 31) == 0) wsum[tid >> 5] = p;
    __syncthreads();
    if (tid == 0) {
        float s = wsum[0] + wsum[1] + wsum[2] + wsum[3] + b2[0];
        float bta = 1.0f / (1.0f + expf(-s));
        bta = fminf(fmaxf(bta, 1e-6f), 1.0f - 1e-6f);
        out[row] = bta;
    }
}

// ---------------- launch ----------------
extern "C" void kernel_launch(void* const* d_in, const int* in_sizes, int n_in,
                              void* d_out, int out_size) {
    const float* x_raw = (const float*)d_in[0];
    const float* in_w  = (const float*)d_in[2];
    const float* in_b  = (const float*)d_in[3];
    const float* ln1_s = (const float*)d_in[4];
    const float* ln1_b = (const float*)d_in[5];
    const float* qkv_w = (const float*)d_in[6];
    const float* qkv_b = (const float*)d_in[7];
    const float* ao_w  = (const float*)d_in[8];
    const float* ao_b  = (const float*)d_in[9];
    const float* ln2_s = (const float*)d_in[10];
    const float* ln2_b = (const float*)d_in[11];
    const float* f1_w  = (const float*)d_in[12];
    const float* f1_b  = (const float*)d_in[13];
    const float* f2_w  = (const float*)d_in[14];
    const float* f2_b  = (const float*)d_in[15];
    const float* lat1_w = (const float*)d_in[16];
    const float* lat1_b = (const float*)d_in[17];
    const float* lat2_w = (const float*)d_in[18];
    const float* lat2_b = (const float*)d_in[19];
    const float* b1_w  = (const float*)d_in[20];
    const float* b1_b  = (const float*)d_in[21];
    const float* b2_w  = (const float*)d_in[22];
    const float* b2_b  = (const float*)d_in[23];
    float* out = (float*)d_out;

    // mask precompute
    etaphi_kernel<<<(NTOK + 255) / 256, 256>>>(x_raw);
    nbr_kernel<<<NTOK, 256>>>();

    // input projection + LN1(layer0) stats:  g_x = x_raw @ in_w^T + in_b
    gemm2<NTOK, HDIM, 16, 32, 128, 0, 0, 0, 1, 0, 0>
        <<<dim3(1, NTOK / 32), 256>>>(x_raw, in_w, in_b, nullptr, nullptr);

    for (int l = 0; l < NLAYER; l++) {
        const float* l1s = ln1_s + l * HDIM;
        const float* l1b = ln1_b + l * HDIM;
        const float* qw  = qkv_w + l * QKVDIM * HDIM;
        const float* qb  = qkv_b + l * QKVDIM;
        const float* aw  = ao_w + l * HDIM * HDIM;
        const float* ab  = ao_b + l * HDIM;
        const float* l2s = ln2_s + l * HDIM;
        const float* l2b = ln2_b + l * HDIM;
        const float* w1  = f1_w + l * FFDIM * HDIM;
        const float* wb1 = f1_b + l * FFDIM;
        const float* w2  = f2_w + l * HDIM * FFDIM;
        const float* wb2 = f2_b + l * HDIM;

        // g_qkv = LN1(g_x) @ qw^T + qb
        gemm2<NTOK, QKVDIM, HDIM, 64, 64, 1, 0, 0, 0, 1, 1>
            <<<dim3(QKVDIM / 64, NTOK / 64), 256>>>(nullptr, qw, qb, l1s, l1b);

        attn_kernel<<<NTOK, HDIM>>>();

        // g_x += g_attn @ aw^T + ab ; epilogue -> LN2 stats
        gemm2<NTOK, HDIM, HDIM, 32, 128, 0, 0, 1, 1, 2, 0>
            <<<dim3(1, NTOK / 32), 256>>>(nullptr, aw, ab, nullptr, nullptr);

        // g_ff = relu(LN2(g_x) @ w1^T + wb1)
        gemm2<NTOK, FFDIM, HDIM, 64, 64, 1, 1, 0, 0, 1, 2>
            <<<dim3(FFDIM / 64, NTOK / 64), 256>>>(nullptr, w1, wb1, l2s, l2b);

        // g_x += g_ff @ w2^T + wb2 ; epilogue -> next-layer LN1 stats
        gemm2<NTOK, HDIM, FFDIM, 32, 128, 0, 0, 1, 1, 3, 0>
            <<<dim3(1, NTOK / 32), 256>>>(nullptr, w2, wb2, nullptr, nullptr);
    }

    // heads: beta -> out[0:4096], lat -> out[4096:4096+4096*16]
    beta_head_kernel<<<NTOK, HDIM>>>(b1_w, b1_b, b2_w, b2_b, out);
    lat_head_kernel<<<NTOK, HDIM>>>(lat1_w, lat1_b, lat2_w, lat2_b, out + NTOK);
}